// round 1
// baseline (speedup 1.0000x reference)
#include <cuda_runtime.h>
#include <cuda_bf16.h>
#include <cstdint>

#define N_NODES   100000
#define NUM_E     1600000
#define DIM_IN    64
#define HDIM      128
#define NLAYERS   3
#define NGRAPHS   512
#define NCLASSES  6
#define LN_EPS    1e-5f

// ---------------- scratch (device globals; no allocation allowed) ----------------
__device__ float    g_h[(size_t)N_NODES * HDIM];      // node features (updated in place per layer)
__device__ float    g_aggr[(size_t)N_NODES * HDIM];   // neighbor sum
__device__ float    g_invdeg[N_NODES];
__device__ int      g_deg[N_NODES];
__device__ float    g_gate[N_NODES];                  // gate logits, then exp(gate-max)
__device__ unsigned g_gmax_ord[NGRAPHS];
__device__ float    g_gsum[NGRAPHS];
__device__ float    g_pooled[NGRAPHS * HDIM];

// ---------------- helpers ----------------
__device__ __forceinline__ unsigned float_to_ord(float f) {
    unsigned u = __float_as_uint(f);
    return (u & 0x80000000u) ? ~u : (u | 0x80000000u);
}
__device__ __forceinline__ float ord_to_float(unsigned u) {
    return __uint_as_float((u & 0x80000000u) ? (u & 0x7fffffffu) : ~u);
}
__device__ __forceinline__ void red_add_v4(float* addr, float a, float b, float c, float d) {
    asm volatile("red.global.add.v4.f32 [%0], {%1,%2,%3,%4};"
                 :: "l"(addr), "f"(a), "f"(b), "f"(c), "f"(d) : "memory");
}

// ---------------- init: zero accumulators ----------------
__global__ void init_kernel() {
    int i = blockIdx.x * blockDim.x + threadIdx.x;
    int stride = gridDim.x * blockDim.x;
    for (int idx = i; idx < N_NODES; idx += stride) g_deg[idx] = 0;
    for (int idx = i; idx < NGRAPHS; idx += stride) { g_gmax_ord[idx] = 0u; g_gsum[idx] = 0.0f; }
    for (int idx = i; idx < NGRAPHS * HDIM; idx += stride) g_pooled[idx] = 0.0f;
}

__global__ void zero_aggr_kernel() {
    size_t i = (size_t)(blockIdx.x * blockDim.x + threadIdx.x);
    size_t stride = (size_t)gridDim.x * blockDim.x;
    float4* p = reinterpret_cast<float4*>(g_aggr);
    size_t n4 = (size_t)N_NODES * HDIM / 4;
    for (size_t idx = i; idx < n4; idx += stride) p[idx] = make_float4(0.f, 0.f, 0.f, 0.f);
}

// ---------------- projection: h = relu(x @ proj_w + b)  [N,64]@[64,128] ----------------
__global__ void __launch_bounds__(128) proj_kernel(const float* __restrict__ x,
                                                   const float* __restrict__ w,
                                                   const float* __restrict__ b) {
    int c = threadIdx.x;  // output column 0..127
    float wr[DIM_IN];
#pragma unroll
    for (int k = 0; k < DIM_IN; k++) wr[k] = w[k * HDIM + c];
    float bias = b[c];
    __shared__ float sx[DIM_IN];
    for (int row = blockIdx.x; row < N_NODES; row += gridDim.x) {
        if (c < DIM_IN) sx[c] = x[(size_t)row * DIM_IN + c];
        __syncthreads();
        float acc = bias;
#pragma unroll
        for (int k = 0; k < DIM_IN; k++) acc += sx[k] * wr[k];
        g_h[(size_t)row * HDIM + c] = fmaxf(acc, 0.0f);
        __syncthreads();
    }
}

// ---------------- degree ----------------
__global__ void deg_kernel(const int* __restrict__ ei) {
    int i = blockIdx.x * blockDim.x + threadIdx.x;
    int stride = gridDim.x * blockDim.x;
    for (int e = i; e < NUM_E; e += stride) {
        int dst = ei[NUM_E + e];
        atomicAdd(&g_deg[dst], 1);
    }
}
__global__ void invdeg_kernel() {
    int i = blockIdx.x * blockDim.x + threadIdx.x;
    int stride = gridDim.x * blockDim.x;
    for (int idx = i; idx < N_NODES; idx += stride) {
        float d = (float)g_deg[idx];
        g_invdeg[idx] = 1.0f / fmaxf(d, 1.0f);
    }
}

// ---------------- edge scatter: aggr[dst] += h[src]  (warp per edge, v4 red) ----------------
__global__ void __launch_bounds__(256) scatter_kernel(const int* __restrict__ ei) {
    int gw = (blockIdx.x * blockDim.x + threadIdx.x) >> 5;
    int lane = threadIdx.x & 31;
    int nwarps = (gridDim.x * blockDim.x) >> 5;
    for (int e = gw; e < NUM_E; e += nwarps) {
        int src = ei[e];
        int dst = ei[NUM_E + e];
        const float4 v = *reinterpret_cast<const float4*>(g_h + (size_t)src * HDIM + lane * 4);
        red_add_v4(g_aggr + (size_t)dst * HDIM + lane * 4, v.x, v.y, v.z, v.w);
    }
}

// ---------------- fused: h = ELU(LN((aggr/deg)@Wl + bl + h@Wr)) + h ----------------
// 256 threads: tid<128 own Wl column c (role A, also does LN+epilogue),
//              tid>=128 own Wr column c (role B).
__global__ void __launch_bounds__(256) gemmln_kernel(const float* __restrict__ wl,
                                                     const float* __restrict__ bl,
                                                     const float* __restrict__ wr,
                                                     const float* __restrict__ lg,
                                                     const float* __restrict__ lb) {
    int tid = threadIdx.x;
    int c = tid & 127;
    bool roleA = tid < 128;
    float w[HDIM];
    const float* W = roleA ? wl : wr;
#pragma unroll
    for (int k = 0; k < HDIM; k++) w[k] = W[k * HDIM + c];
    float bias = bl[c];
    float gam = lg[c], bet = lb[c];

    __shared__ float s_agg[HDIM];
    __shared__ float s_h[HDIM];
    __shared__ float s_part[HDIM];
    __shared__ float s_red[8];

    for (int row = blockIdx.x; row < N_NODES; row += gridDim.x) {
        if (roleA) s_agg[c] = g_aggr[(size_t)row * HDIM + c] * g_invdeg[row];
        else       s_h[c]   = g_h[(size_t)row * HDIM + c];
        __syncthreads();
        const float* in = roleA ? s_agg : s_h;
        float p = 0.0f;
#pragma unroll
        for (int k = 0; k < HDIM; k++) p += in[k] * w[k];
        if (!roleA) s_part[c] = p;
        __syncthreads();
        if (roleA) {
            float y = p + s_part[c] + bias;
            float s = y, s2 = y * y;
#pragma unroll
            for (int o = 16; o; o >>= 1) {
                s  += __shfl_xor_sync(0xffffffffu, s,  o);
                s2 += __shfl_xor_sync(0xffffffffu, s2, o);
            }
            if ((c & 31) == 0) { s_red[c >> 5] = s; s_red[4 + (c >> 5)] = s2; }
            s_part[c] = y;  // stash y for after reduction
        }
        __syncthreads();
        if (roleA) {
            float y   = s_part[c];
            float sum = s_red[0] + s_red[1] + s_red[2] + s_red[3];
            float sq  = s_red[4] + s_red[5] + s_red[6] + s_red[7];
            float mu  = sum * (1.0f / HDIM);
            float var = sq * (1.0f / HDIM) - mu * mu;
            float nrm = (y - mu) * rsqrtf(var + LN_EPS) * gam + bet;
            float e   = nrm > 0.0f ? nrm : expm1f(nrm);
            g_h[(size_t)row * HDIM + c] = e + s_h[c];
        }
        __syncthreads();
    }
}

// ---------------- gate: gate[i] = relu(h@gw1+gb1)@gw2 + gb2; track per-graph max ----------------
__global__ void __launch_bounds__(64) gate_kernel(const float* __restrict__ gw1,
                                                  const float* __restrict__ gb1,
                                                  const float* __restrict__ gw2,
                                                  const float* __restrict__ gb2,
                                                  const int* __restrict__ batch) {
    int j = threadIdx.x;  // 0..63 hidden unit
    float w[HDIM];
#pragma unroll
    for (int k = 0; k < HDIM; k++) w[k] = gw1[k * 64 + j];
    float b1 = gb1[j], w2 = gw2[j], b2 = gb2[0];
    __shared__ float sh[HDIM];
    __shared__ float sp[2];
    for (int row = blockIdx.x; row < N_NODES; row += gridDim.x) {
        sh[j]      = g_h[(size_t)row * HDIM + j];
        sh[j + 64] = g_h[(size_t)row * HDIM + j + 64];
        __syncthreads();
        float acc = b1;
#pragma unroll
        for (int k = 0; k < HDIM; k++) acc += sh[k] * w[k];
        float t = fmaxf(acc, 0.0f) * w2;
#pragma unroll
        for (int o = 16; o; o >>= 1) t += __shfl_xor_sync(0xffffffffu, t, o);
        if ((j & 31) == 0) sp[j >> 5] = t;
        __syncthreads();
        if (j == 0) {
            float gate = sp[0] + sp[1] + b2;
            g_gate[row] = gate;
            atomicMax(&g_gmax_ord[batch[row]], float_to_ord(gate));
        }
        __syncthreads();
    }
}

// ---------------- segment softmax numerator + denominator ----------------
__global__ void eg_kernel(const int* __restrict__ batch) {
    int i = blockIdx.x * blockDim.x + threadIdx.x;
    int stride = gridDim.x * blockDim.x;
    for (int idx = i; idx < N_NODES; idx += stride) {
        int b = batch[idx];
        float m = ord_to_float(g_gmax_ord[b]);
        float e = expf(g_gate[idx] - m);
        g_gate[idx] = e;
        atomicAdd(&g_gsum[b], e);
    }
}

// ---------------- pooled[b] += alpha_i * h[i] ----------------
__global__ void __launch_bounds__(256) pooled_kernel(const int* __restrict__ batch) {
    int gw = (blockIdx.x * blockDim.x + threadIdx.x) >> 5;
    int lane = threadIdx.x & 31;
    int nwarps = (gridDim.x * blockDim.x) >> 5;
    for (int row = gw; row < N_NODES; row += nwarps) {
        int b = batch[row];
        float alpha = g_gate[row] / g_gsum[b];
        const float4 v = *reinterpret_cast<const float4*>(g_h + (size_t)row * HDIM + lane * 4);
        red_add_v4(g_pooled + (size_t)b * HDIM + lane * 4,
                   v.x * alpha, v.y * alpha, v.z * alpha, v.w * alpha);
    }
}

// ---------------- classifier: out = relu(pooled@w1+b1)@w2 + b2 ----------------
__global__ void __launch_bounds__(64) cls_kernel(const float* __restrict__ w1,
                                                 const float* __restrict__ b1,
                                                 const float* __restrict__ w2,
                                                 const float* __restrict__ b2,
                                                 float* __restrict__ out) {
    int g = blockIdx.x;
    int j = threadIdx.x;  // 0..63
    __shared__ float sp[HDIM];
    __shared__ float shid[64];
    sp[j]      = g_pooled[(size_t)g * HDIM + j];
    sp[j + 64] = g_pooled[(size_t)g * HDIM + j + 64];
    __syncthreads();
    float acc = b1[j];
#pragma unroll
    for (int k = 0; k < HDIM; k++) acc += sp[k] * w1[k * 64 + j];
    shid[j] = fmaxf(acc, 0.0f);
    __syncthreads();
    if (j < NCLASSES) {
        float o = b2[j];
#pragma unroll
        for (int k = 0; k < 64; k++) o += shid[k] * w2[k * NCLASSES + j];
        out[(size_t)g * NCLASSES + j] = o;
    }
}

// ---------------- launch ----------------
extern "C" void kernel_launch(void* const* d_in, const int* in_sizes, int n_in,
                              void* d_out, int out_size) {
    const float* x       = (const float*)d_in[0];
    const int*   ei      = (const int*)d_in[1];   // [2,E] int32 (JAX x64 disabled)
    const int*   batch   = (const int*)d_in[2];
    const float* proj_w  = (const float*)d_in[3];
    const float* proj_b  = (const float*)d_in[4];
    const float* lin_l_w = (const float*)d_in[5];
    const float* lin_l_b = (const float*)d_in[6];
    const float* lin_r_w = (const float*)d_in[7];
    const float* ln_g    = (const float*)d_in[8];
    const float* ln_b    = (const float*)d_in[9];
    const float* gate_w1 = (const float*)d_in[10];
    const float* gate_b1 = (const float*)d_in[11];
    const float* gate_w2 = (const float*)d_in[12];
    const float* gate_b2 = (const float*)d_in[13];
    const float* cls_w1  = (const float*)d_in[14];
    const float* cls_b1  = (const float*)d_in[15];
    const float* cls_w2  = (const float*)d_in[16];
    const float* cls_b2  = (const float*)d_in[17];
    float* out = (float*)d_out;

    init_kernel<<<512, 256>>>();
    proj_kernel<<<2048, 128>>>(x, proj_w, proj_b);
    deg_kernel<<<2048, 256>>>(ei);
    invdeg_kernel<<<392, 256>>>();

    for (int l = 0; l < NLAYERS; l++) {
        zero_aggr_kernel<<<1184, 256>>>();
        scatter_kernel<<<2048, 256>>>(ei);
        gemmln_kernel<<<148, 256>>>(lin_l_w + (size_t)l * HDIM * HDIM,
                                    lin_l_b + (size_t)l * HDIM,
                                    lin_r_w + (size_t)l * HDIM * HDIM,
                                    ln_g + (size_t)l * HDIM,
                                    ln_b + (size_t)l * HDIM);
    }

    gate_kernel<<<2048, 64>>>(gate_w1, gate_b1, gate_w2, gate_b2, batch);
    eg_kernel<<<392, 256>>>(batch);
    pooled_kernel<<<2048, 256>>>(batch);
    cls_kernel<<<NGRAPHS, 64>>>(cls_w1, cls_b1, cls_w2, cls_b2, out);
}

// round 2
// speedup vs baseline: 3.5348x; 3.5348x over previous
#include <cuda_runtime.h>
#include <cuda_bf16.h>
#include <cstdint>

#define N_NODES   100000
#define NUM_E     1600000
#define DIM_IN    64
#define HDIM      128
#define NLAYERS   3
#define NGRAPHS   512
#define NCLASSES  6
#define LN_EPS    1e-5f
#define NBLK      98          // ceil(100000/1024)

// ---------------- scratch ----------------
__device__ float    g_h[(size_t)N_NODES * HDIM];
__device__ float    g_aggr[(size_t)N_NODES * HDIM];   // already normalized by 1/deg
__device__ float    g_invdeg[N_NODES];
__device__ int      g_deg[N_NODES];
__device__ int      g_off[N_NODES + 1];
__device__ int      g_cursor[N_NODES];
__device__ int      g_csr[NUM_E];
__device__ int      g_bsum[NBLK];
__device__ int      g_boff[NBLK];
__device__ float    g_gate[N_NODES];
__device__ unsigned g_gmax_ord[NGRAPHS];
__device__ float    g_gsum[NGRAPHS];
__device__ float    g_pooled[NGRAPHS * HDIM];

// ---------------- helpers ----------------
__device__ __forceinline__ unsigned float_to_ord(float f) {
    unsigned u = __float_as_uint(f);
    return (u & 0x80000000u) ? ~u : (u | 0x80000000u);
}
__device__ __forceinline__ float ord_to_float(unsigned u) {
    return __uint_as_float((u & 0x80000000u) ? (u & 0x7fffffffu) : ~u);
}
__device__ __forceinline__ unsigned tf32u(float x) {
    unsigned r; asm("cvt.rna.tf32.f32 %0, %1;" : "=r"(r) : "f"(x)); return r;
}
__device__ __forceinline__ float tf32f(float x) {
    float r; asm("cvt.rna.tf32.f32 %0, %1;" : "=f"(r) : "f"(x)); return r;
}
__device__ __forceinline__ void mma_tf32(float& d0, float& d1, float& d2, float& d3,
                                         unsigned a0, unsigned a1, unsigned a2, unsigned a3,
                                         unsigned b0, unsigned b1) {
    asm volatile("mma.sync.aligned.m16n8k8.row.col.f32.tf32.tf32.f32 "
                 "{%0,%1,%2,%3},{%4,%5,%6,%7},{%8,%9},{%0,%1,%2,%3};"
                 : "+f"(d0), "+f"(d1), "+f"(d2), "+f"(d3)
                 : "r"(a0), "r"(a1), "r"(a2), "r"(a3), "r"(b0), "r"(b1));
}

// ---------------- init ----------------
__global__ void init_kernel() {
    int i = blockIdx.x * blockDim.x + threadIdx.x;
    int stride = gridDim.x * blockDim.x;
    for (int idx = i; idx < N_NODES; idx += stride) g_deg[idx] = 0;
    for (int idx = i; idx < NGRAPHS; idx += stride) { g_gmax_ord[idx] = 0u; g_gsum[idx] = 0.0f; }
    for (int idx = i; idx < NGRAPHS * HDIM; idx += stride) g_pooled[idx] = 0.0f;
}

// ---------------- degree ----------------
__global__ void deg_kernel(const int* __restrict__ ei) {
    int i = blockIdx.x * blockDim.x + threadIdx.x;
    int stride = gridDim.x * blockDim.x;
    for (int e = i; e < NUM_E; e += stride) atomicAdd(&g_deg[ei[NUM_E + e]], 1);
}

// ---------------- CSR build: scan over degrees ----------------
__global__ void __launch_bounds__(1024) scan_a_kernel() {
    int i = blockIdx.x * 1024 + threadIdx.x;
    int lane = threadIdx.x & 31;
    int v = (i < N_NODES) ? g_deg[i] : 0;
#pragma unroll
    for (int o = 16; o; o >>= 1) v += __shfl_xor_sync(0xffffffffu, v, o);
    __shared__ int wsum[32];
    if (lane == 0) wsum[threadIdx.x >> 5] = v;
    __syncthreads();
    if (threadIdx.x < 32) {
        int t = wsum[threadIdx.x];
#pragma unroll
        for (int o = 16; o; o >>= 1) t += __shfl_xor_sync(0xffffffffu, t, o);
        if (threadIdx.x == 0) g_bsum[blockIdx.x] = t;
    }
}
__global__ void __launch_bounds__(128) scan_b_kernel() {
    __shared__ int sm[128];
    int t = threadIdx.x;
    int v = (t < NBLK) ? g_bsum[t] : 0;
    sm[t] = v; __syncthreads();
    for (int o = 1; o < 128; o <<= 1) {
        int tmp = (t >= o) ? sm[t - o] : 0;
        __syncthreads();
        sm[t] += tmp;
        __syncthreads();
    }
    if (t < NBLK) g_boff[t] = sm[t] - v;
    if (t == NBLK - 1) g_off[N_NODES] = sm[t];
}
__global__ void __launch_bounds__(1024) scan_c_kernel() {
    __shared__ int sm[1024];
    int t = threadIdx.x;
    int i = blockIdx.x * 1024 + t;
    int v = (i < N_NODES) ? g_deg[i] : 0;
    sm[t] = v; __syncthreads();
    for (int o = 1; o < 1024; o <<= 1) {
        int tmp = (t >= o) ? sm[t - o] : 0;
        __syncthreads();
        sm[t] += tmp;
        __syncthreads();
    }
    if (i < N_NODES) {
        int off = g_boff[blockIdx.x] + sm[t] - v;
        g_off[i] = off;
        g_cursor[i] = off;
    }
}
__global__ void fill_kernel(const int* __restrict__ ei) {
    int i = blockIdx.x * blockDim.x + threadIdx.x;
    int stride = gridDim.x * blockDim.x;
    for (int e = i; e < NUM_E; e += stride) {
        int src = ei[e];
        int dst = ei[NUM_E + e];
        int p = atomicAdd(&g_cursor[dst], 1);
        g_csr[p] = src;
    }
}
__global__ void invdeg_kernel() {
    int i = blockIdx.x * blockDim.x + threadIdx.x;
    int stride = gridDim.x * blockDim.x;
    for (int idx = i; idx < N_NODES; idx += stride)
        g_invdeg[idx] = 1.0f / fmaxf((float)g_deg[idx], 1.0f);
}

// ---------------- projection: h = relu(x @ proj_w + b), 4 rows/iter ----------------
__global__ void __launch_bounds__(128) proj_kernel(const float* __restrict__ x,
                                                   const float* __restrict__ w,
                                                   const float* __restrict__ b) {
    int c = threadIdx.x;
    float wr[DIM_IN];
#pragma unroll
    for (int k = 0; k < DIM_IN; k++) wr[k] = w[k * HDIM + c];
    float bias = b[c];
    __shared__ float sx[4][DIM_IN];
    for (int r0 = blockIdx.x * 4; r0 < N_NODES; r0 += gridDim.x * 4) {
        if (c < 64) {
            int r = c >> 4; int c4 = (c & 15) * 4;
            int row = r0 + r;
            float4 v = make_float4(0.f, 0.f, 0.f, 0.f);
            if (row < N_NODES) v = *(const float4*)(x + (size_t)row * DIM_IN + c4);
            *(float4*)&sx[r][c4] = v;
        }
        __syncthreads();
        float a0 = bias, a1 = bias, a2 = bias, a3 = bias;
#pragma unroll
        for (int k = 0; k < DIM_IN; k++) {
            float wk = wr[k];
            a0 += sx[0][k] * wk; a1 += sx[1][k] * wk;
            a2 += sx[2][k] * wk; a3 += sx[3][k] * wk;
        }
        if (r0 + 0 < N_NODES) g_h[(size_t)(r0 + 0) * HDIM + c] = fmaxf(a0, 0.f);
        if (r0 + 1 < N_NODES) g_h[(size_t)(r0 + 1) * HDIM + c] = fmaxf(a1, 0.f);
        if (r0 + 2 < N_NODES) g_h[(size_t)(r0 + 2) * HDIM + c] = fmaxf(a2, 0.f);
        if (r0 + 3 < N_NODES) g_h[(size_t)(r0 + 3) * HDIM + c] = fmaxf(a3, 0.f);
        __syncthreads();
    }
}

// ---------------- aggregation: warp-per-node CSR gather, fused 1/deg ----------------
__global__ void __launch_bounds__(256) aggregate_kernel() {
    int gw = (blockIdx.x * blockDim.x + threadIdx.x) >> 5;
    int lane = threadIdx.x & 31;
    int nw = (gridDim.x * blockDim.x) >> 5;
    for (int v = gw; v < N_NODES; v += nw) {
        int beg = g_off[v], end = g_off[v + 1];
        float x0 = 0.f, x1 = 0.f, x2 = 0.f, x3 = 0.f;
        int e = beg;
        for (; e + 2 <= end; e += 2) {
            int s0 = g_csr[e], s1 = g_csr[e + 1];
            float4 u = *((const float4*)(g_h + (size_t)s0 * HDIM) + lane);
            float4 w = *((const float4*)(g_h + (size_t)s1 * HDIM) + lane);
            x0 += u.x + w.x; x1 += u.y + w.y; x2 += u.z + w.z; x3 += u.w + w.w;
        }
        if (e < end) {
            int s0 = g_csr[e];
            float4 u = *((const float4*)(g_h + (size_t)s0 * HDIM) + lane);
            x0 += u.x; x1 += u.y; x2 += u.z; x3 += u.w;
        }
        float inv = g_invdeg[v];
        float4 o = make_float4(x0 * inv, x1 * inv, x2 * inv, x3 * inv);
        *((float4*)(g_aggr + (size_t)v * HDIM) + lane) = o;
    }
}

// ---------------- fused layer: Y = [aggr|h] @ [Wl;Wr] + bl; h = ELU(LN(Y)) + h ----------------
// tf32 mma.m16n8k8. CTA = 128 thr / 4 warps, tile M=64 (warp m16), N=128, K=256.
__global__ void __launch_bounds__(128) layer_kernel(const float* __restrict__ wl,
                                                    const float* __restrict__ bl,
                                                    const float* __restrict__ wr,
                                                    const float* __restrict__ lg,
                                                    const float* __restrict__ lb) {
    __shared__ float sB[2][8 * 132];
    __shared__ float sGB[384];  // gamma | beta | bias
    int tid = threadIdx.x;
    int lane = tid & 31, warp = tid >> 5;
    int tg = lane & 3, g = lane >> 2;
    sGB[tid] = lg[tid]; sGB[128 + tid] = lb[tid]; sGB[256 + tid] = bl[tid];

    int rowbase = blockIdx.x * 64;
    int grow0 = rowbase + warp * 16 + g;
    int grow1 = grow0 + 8;
    bool v0 = grow0 < N_NODES, v1 = grow1 < N_NODES;

    // stage B chunk 0 (rows k=0..7 of Wl), converted to tf32
    for (int i = tid; i < 256; i += 128) {
        int k = i >> 5; int c4 = (i & 31) * 4;
        float4 v = *(const float4*)(wl + k * HDIM + c4);
        float* d = &sB[0][k * 132 + c4];
        d[0] = tf32f(v.x); d[1] = tf32f(v.y); d[2] = tf32f(v.z); d[3] = tf32f(v.w);
    }
    __syncthreads();

    float acc[16][4];
#pragma unroll
    for (int t = 0; t < 16; t++) { acc[t][0] = 0.f; acc[t][1] = 0.f; acc[t][2] = 0.f; acc[t][3] = 0.f; }

    // preload A frags for step 0 (cols 0..7 of aggr)
    unsigned a0 = 0, a1 = 0, a2 = 0, a3 = 0;
    {
        const float* p0 = g_aggr + (size_t)grow0 * HDIM + tg;
        const float* p1 = g_aggr + (size_t)grow1 * HDIM + tg;
        if (v0) { a0 = tf32u(p0[0]); a2 = tf32u(p0[4]); }
        if (v1) { a1 = tf32u(p1[0]); a3 = tf32u(p1[4]); }
    }

    for (int s = 0; s < 32; s++) {
        int cur = s & 1;
        unsigned na0 = 0, na1 = 0, na2 = 0, na3 = 0;
        if (s < 31) {
            int kk = (s + 1) * 8;
            const float* src0 = (kk < HDIM) ? (g_aggr + (size_t)grow0 * HDIM + kk + tg)
                                            : (g_h + (size_t)grow0 * HDIM + (kk - HDIM) + tg);
            const float* src1 = (kk < HDIM) ? (g_aggr + (size_t)grow1 * HDIM + kk + tg)
                                            : (g_h + (size_t)grow1 * HDIM + (kk - HDIM) + tg);
            if (v0) { na0 = tf32u(src0[0]); na2 = tf32u(src0[4]); }
            if (v1) { na1 = tf32u(src1[0]); na3 = tf32u(src1[4]); }
            const float* wbase = (kk < HDIM) ? (wl + kk * HDIM) : (wr + (kk - HDIM) * HDIM);
            for (int i = tid; i < 256; i += 128) {
                int k = i >> 5; int c4 = (i & 31) * 4;
                float4 v = *(const float4*)(wbase + k * HDIM + c4);
                float* d = &sB[cur ^ 1][k * 132 + c4];
                d[0] = tf32f(v.x); d[1] = tf32f(v.y); d[2] = tf32f(v.z); d[3] = tf32f(v.w);
            }
        }
        const float* bb = &sB[cur][tg * 132 + g];
#pragma unroll
        for (int t = 0; t < 16; t++) {
            unsigned b0 = __float_as_uint(bb[t * 8]);
            unsigned b1 = __float_as_uint(bb[t * 8 + 4 * 132]);
            mma_tf32(acc[t][0], acc[t][1], acc[t][2], acc[t][3], a0, a1, a2, a3, b0, b1);
        }
        a0 = na0; a1 = na1; a2 = na2; a3 = na3;
        __syncthreads();
    }

    // epilogue: bias, LN (rows warp-local), ELU, residual
    float s0 = 0.f, q0 = 0.f, s1 = 0.f, q1 = 0.f;
#pragma unroll
    for (int t = 0; t < 16; t++) {
        int c = t * 8 + tg * 2;
        float bb0 = sGB[256 + c], bb1 = sGB[256 + c + 1];
        acc[t][0] += bb0; acc[t][1] += bb1; acc[t][2] += bb0; acc[t][3] += bb1;
        s0 += acc[t][0] + acc[t][1]; q0 += acc[t][0] * acc[t][0] + acc[t][1] * acc[t][1];
        s1 += acc[t][2] + acc[t][3]; q1 += acc[t][2] * acc[t][2] + acc[t][3] * acc[t][3];
    }
#pragma unroll
    for (int o = 1; o <= 2; o <<= 1) {
        s0 += __shfl_xor_sync(0xffffffffu, s0, o);
        q0 += __shfl_xor_sync(0xffffffffu, q0, o);
        s1 += __shfl_xor_sync(0xffffffffu, s1, o);
        q1 += __shfl_xor_sync(0xffffffffu, q1, o);
    }
    float mu0 = s0 * (1.0f / HDIM), mu1 = s1 * (1.0f / HDIM);
    float rs0 = rsqrtf(q0 * (1.0f / HDIM) - mu0 * mu0 + LN_EPS);
    float rs1 = rsqrtf(q1 * (1.0f / HDIM) - mu1 * mu1 + LN_EPS);
    if (v0) {
#pragma unroll
        for (int t = 0; t < 16; t++) {
            int c = t * 8 + tg * 2;
            float n0 = (acc[t][0] - mu0) * rs0 * sGB[c] + sGB[128 + c];
            float n1 = (acc[t][1] - mu0) * rs0 * sGB[c + 1] + sGB[128 + c + 1];
            float e0 = n0 > 0.f ? n0 : expm1f(n0);
            float e1 = n1 > 0.f ? n1 : expm1f(n1);
            float* hp = g_h + (size_t)grow0 * HDIM + c;
            float2 o = make_float2(e0 + hp[0], e1 + hp[1]);
            *(float2*)hp = o;
        }
    }
    if (v1) {
#pragma unroll
        for (int t = 0; t < 16; t++) {
            int c = t * 8 + tg * 2;
            float n0 = (acc[t][2] - mu1) * rs1 * sGB[c] + sGB[128 + c];
            float n1 = (acc[t][3] - mu1) * rs1 * sGB[c + 1] + sGB[128 + c + 1];
            float e0 = n0 > 0.f ? n0 : expm1f(n0);
            float e1 = n1 > 0.f ? n1 : expm1f(n1);
            float* hp = g_h + (size_t)grow1 * HDIM + c;
            float2 o = make_float2(e0 + hp[0], e1 + hp[1]);
            *(float2*)hp = o;
        }
    }
}

// ---------------- gate, 4 rows/iter ----------------
__global__ void __launch_bounds__(64) gate_kernel(const float* __restrict__ gw1,
                                                  const float* __restrict__ gb1,
                                                  const float* __restrict__ gw2,
                                                  const float* __restrict__ gb2,
                                                  const int* __restrict__ batch) {
    int j = threadIdx.x, lane = j & 31, wid = j >> 5;
    float w[HDIM];
#pragma unroll
    for (int k = 0; k < HDIM; k++) w[k] = gw1[k * 64 + j];
    float b1 = gb1[j], w2 = gw2[j], b2v = gb2[0];
    __shared__ float sh[4][HDIM];
    __shared__ float sp[4][2];
    for (int r0 = blockIdx.x * 4; r0 < N_NODES; r0 += gridDim.x * 4) {
#pragma unroll
        for (int p = 0; p < 2; p++) {
            int idx = p * 64 + j;
            int r = idx >> 5; int c4 = (idx & 31) * 4;
            int row = r0 + r;
            float4 v = make_float4(0.f, 0.f, 0.f, 0.f);
            if (row < N_NODES) v = *(const float4*)(g_h + (size_t)row * HDIM + c4);
            *(float4*)&sh[r][c4] = v;
        }
        __syncthreads();
        float a0 = b1, a1 = b1, a2 = b1, a3 = b1;
#pragma unroll
        for (int k = 0; k < HDIM; k++) {
            float wk = w[k];
            a0 += sh[0][k] * wk; a1 += sh[1][k] * wk;
            a2 += sh[2][k] * wk; a3 += sh[3][k] * wk;
        }
        a0 = fmaxf(a0, 0.f) * w2; a1 = fmaxf(a1, 0.f) * w2;
        a2 = fmaxf(a2, 0.f) * w2; a3 = fmaxf(a3, 0.f) * w2;
#pragma unroll
        for (int o = 16; o; o >>= 1) {
            a0 += __shfl_xor_sync(0xffffffffu, a0, o);
            a1 += __shfl_xor_sync(0xffffffffu, a1, o);
            a2 += __shfl_xor_sync(0xffffffffu, a2, o);
            a3 += __shfl_xor_sync(0xffffffffu, a3, o);
        }
        if (lane == 0) { sp[0][wid] = a0; sp[1][wid] = a1; sp[2][wid] = a2; sp[3][wid] = a3; }
        __syncthreads();
        if (j < 4 && r0 + j < N_NODES) {
            float gate = sp[j][0] + sp[j][1] + b2v;
            g_gate[r0 + j] = gate;
            atomicMax(&g_gmax_ord[batch[r0 + j]], float_to_ord(gate));
        }
        __syncthreads();
    }
}

__global__ void eg_kernel(const int* __restrict__ batch) {
    int i = blockIdx.x * blockDim.x + threadIdx.x;
    int stride = gridDim.x * blockDim.x;
    for (int idx = i; idx < N_NODES; idx += stride) {
        int b = batch[idx];
        float m = ord_to_float(g_gmax_ord[b]);
        float e = expf(g_gate[idx] - m);
        g_gate[idx] = e;
        atomicAdd(&g_gsum[b], e);
    }
}

__device__ __forceinline__ void red_add_v4(float* addr, float a, float b, float c, float d) {
    asm volatile("red.global.add.v4.f32 [%0], {%1,%2,%3,%4};"
                 :: "l"(addr), "f"(a), "f"(b), "f"(c), "f"(d) : "memory");
}

__global__ void __launch_bounds__(256) pooled_kernel(const int* __restrict__ batch) {
    int gw = (blockIdx.x * blockDim.x + threadIdx.x) >> 5;
    int lane = threadIdx.x & 31;
    int nw = (gridDim.x * blockDim.x) >> 5;
    for (int row = gw; row < N_NODES; row += nw) {
        int b = batch[row];
        float alpha = g_gate[row] / g_gsum[b];
        const float4 v = *((const float4*)(g_h + (size_t)row * HDIM) + lane);
        red_add_v4(g_pooled + (size_t)b * HDIM + lane * 4,
                   v.x * alpha, v.y * alpha, v.z * alpha, v.w * alpha);
    }
}

__global__ void __launch_bounds__(64) cls_kernel(const float* __restrict__ w1,
                                                 const float* __restrict__ b1,
                                                 const float* __restrict__ w2,
                                                 const float* __restrict__ b2,
                                                 float* __restrict__ out) {
    int gidx = blockIdx.x;
    int j = threadIdx.x;
    __shared__ float sp[HDIM];
    __shared__ float shid[64];
    sp[j] = g_pooled[(size_t)gidx * HDIM + j];
    sp[j + 64] = g_pooled[(size_t)gidx * HDIM + j + 64];
    __syncthreads();
    float acc = b1[j];
#pragma unroll
    for (int k = 0; k < HDIM; k++) acc += sp[k] * w1[k * 64 + j];
    shid[j] = fmaxf(acc, 0.f);
    __syncthreads();
    if (j < NCLASSES) {
        float o = b2[j];
#pragma unroll
        for (int k = 0; k < 64; k++) o += shid[k] * w2[k * NCLASSES + j];
        out[(size_t)gidx * NCLASSES + j] = o;
    }
}

// ---------------- launch ----------------
extern "C" void kernel_launch(void* const* d_in, const int* in_sizes, int n_in,
                              void* d_out, int out_size) {
    const float* x       = (const float*)d_in[0];
    const int*   ei      = (const int*)d_in[1];
    const int*   batch   = (const int*)d_in[2];
    const float* proj_w  = (const float*)d_in[3];
    const float* proj_b  = (const float*)d_in[4];
    const float* lin_l_w = (const float*)d_in[5];
    const float* lin_l_b = (const float*)d_in[6];
    const float* lin_r_w = (const float*)d_in[7];
    const float* ln_g    = (const float*)d_in[8];
    const float* ln_b    = (const float*)d_in[9];
    const float* gate_w1 = (const float*)d_in[10];
    const float* gate_b1 = (const float*)d_in[11];
    const float* gate_w2 = (const float*)d_in[12];
    const float* gate_b2 = (const float*)d_in[13];
    const float* cls_w1  = (const float*)d_in[14];
    const float* cls_b1  = (const float*)d_in[15];
    const float* cls_w2  = (const float*)d_in[16];
    const float* cls_b2  = (const float*)d_in[17];
    float* out = (float*)d_out;

    init_kernel<<<512, 256>>>();
    deg_kernel<<<2048, 256>>>(ei);
    scan_a_kernel<<<NBLK, 1024>>>();
    scan_b_kernel<<<1, 128>>>();
    scan_c_kernel<<<NBLK, 1024>>>();
    fill_kernel<<<2048, 256>>>(ei);
    invdeg_kernel<<<392, 256>>>();
    proj_kernel<<<4096, 128>>>(x, proj_w, proj_b);

    for (int l = 0; l < NLAYERS; l++) {
        aggregate_kernel<<<2048, 256>>>();
        layer_kernel<<<(N_NODES + 63) / 64, 128>>>(lin_l_w + (size_t)l * HDIM * HDIM,
                                                   lin_l_b + (size_t)l * HDIM,
                                                   lin_r_w + (size_t)l * HDIM * HDIM,
                                                   ln_g + (size_t)l * HDIM,
                                                   ln_b + (size_t)l * HDIM);
    }

    gate_kernel<<<2048, 64>>>(gate_w1, gate_b1, gate_w2, gate_b2, batch);
    eg_kernel<<<392, 256>>>(batch);
    pooled_kernel<<<2048, 256>>>(batch);
    cls_kernel<<<NGRAPHS, 64>>>(cls_w1, cls_b1, cls_w2, cls_b2, out);
}

// round 3
// speedup vs baseline: 4.2903x; 1.2137x over previous
#include <cuda_runtime.h>
#include <cuda_bf16.h>
#include <cstdint>

#define N_NODES   100000
#define NUM_E     1600000
#define DIM_IN    64
#define HDIM      128
#define NLAYERS   3
#define NGRAPHS   512
#define NCLASSES  6
#define LN_EPS    1e-5f
#define NBLK      98
#define NTILES    782          // ceil(100000/128)

// ---------------- scratch ----------------
__device__ float    g_h[(size_t)N_NODES * HDIM];
__device__ float    g_aggr[(size_t)N_NODES * HDIM];
__device__ float    g_invdeg[N_NODES];
__device__ int      g_deg[N_NODES];
__device__ int      g_off[N_NODES + 1];
__device__ int      g_cursor[N_NODES];
__device__ int      g_csr[NUM_E];
__device__ int      g_bsum[NBLK];
__device__ int      g_boff[NBLK];
__device__ float    g_gate[N_NODES];
__device__ unsigned g_gmax_ord[NGRAPHS];
__device__ float    g_gsum[NGRAPHS];
__device__ float    g_pooled[NGRAPHS * HDIM];

// ---------------- helpers ----------------
__device__ __forceinline__ unsigned float_to_ord(float f) {
    unsigned u = __float_as_uint(f);
    return (u & 0x80000000u) ? ~u : (u | 0x80000000u);
}
__device__ __forceinline__ float ord_to_float(unsigned u) {
    return __uint_as_float((u & 0x80000000u) ? (u & 0x7fffffffu) : ~u);
}
__device__ __forceinline__ unsigned tf32u(float x) {
    unsigned r; asm("cvt.rna.tf32.f32 %0, %1;" : "=r"(r) : "f"(x)); return r;
}
__device__ __forceinline__ float tf32f(float x) {
    float r; asm("cvt.rna.tf32.f32 %0, %1;" : "=f"(r) : "f"(x)); return r;
}
__device__ __forceinline__ void mma_tf32(float& d0, float& d1, float& d2, float& d3,
                                         unsigned a0, unsigned a1, unsigned a2, unsigned a3,
                                         unsigned b0, unsigned b1) {
    asm volatile("mma.sync.aligned.m16n8k8.row.col.f32.tf32.tf32.f32 "
                 "{%0,%1,%2,%3},{%4,%5,%6,%7},{%8,%9},{%0,%1,%2,%3};"
                 : "+f"(d0), "+f"(d1), "+f"(d2), "+f"(d3)
                 : "r"(a0), "r"(a1), "r"(a2), "r"(a3), "r"(b0), "r"(b1));
}

// ---------------- init / degree / CSR ----------------
__global__ void init_kernel() {
    int i = blockIdx.x * blockDim.x + threadIdx.x;
    int stride = gridDim.x * blockDim.x;
    for (int idx = i; idx < N_NODES; idx += stride) g_deg[idx] = 0;
    for (int idx = i; idx < NGRAPHS; idx += stride) { g_gmax_ord[idx] = 0u; g_gsum[idx] = 0.0f; }
    for (int idx = i; idx < NGRAPHS * HDIM; idx += stride) g_pooled[idx] = 0.0f;
}
__global__ void deg_kernel(const int* __restrict__ ei) {
    int i = blockIdx.x * blockDim.x + threadIdx.x;
    int stride = gridDim.x * blockDim.x;
    for (int e = i; e < NUM_E; e += stride) atomicAdd(&g_deg[ei[NUM_E + e]], 1);
}
__global__ void __launch_bounds__(1024) scan_a_kernel() {
    int i = blockIdx.x * 1024 + threadIdx.x;
    int lane = threadIdx.x & 31;
    int v = (i < N_NODES) ? g_deg[i] : 0;
#pragma unroll
    for (int o = 16; o; o >>= 1) v += __shfl_xor_sync(0xffffffffu, v, o);
    __shared__ int wsum[32];
    if (lane == 0) wsum[threadIdx.x >> 5] = v;
    __syncthreads();
    if (threadIdx.x < 32) {
        int t = wsum[threadIdx.x];
#pragma unroll
        for (int o = 16; o; o >>= 1) t += __shfl_xor_sync(0xffffffffu, t, o);
        if (threadIdx.x == 0) g_bsum[blockIdx.x] = t;
    }
}
__global__ void __launch_bounds__(128) scan_b_kernel() {
    __shared__ int sm[128];
    int t = threadIdx.x;
    int v = (t < NBLK) ? g_bsum[t] : 0;
    sm[t] = v; __syncthreads();
    for (int o = 1; o < 128; o <<= 1) {
        int tmp = (t >= o) ? sm[t - o] : 0;
        __syncthreads();
        sm[t] += tmp;
        __syncthreads();
    }
    if (t < NBLK) g_boff[t] = sm[t] - v;
    if (t == NBLK - 1) g_off[N_NODES] = sm[t];
}
__global__ void __launch_bounds__(1024) scan_c_kernel() {
    __shared__ int sm[1024];
    int t = threadIdx.x;
    int i = blockIdx.x * 1024 + t;
    int v = (i < N_NODES) ? g_deg[i] : 0;
    sm[t] = v; __syncthreads();
    for (int o = 1; o < 1024; o <<= 1) {
        int tmp = (t >= o) ? sm[t - o] : 0;
        __syncthreads();
        sm[t] += tmp;
        __syncthreads();
    }
    if (i < N_NODES) {
        int off = g_boff[blockIdx.x] + sm[t] - v;
        g_off[i] = off;
        g_cursor[i] = off;
    }
}
__global__ void fill_kernel(const int* __restrict__ ei) {
    int i = blockIdx.x * blockDim.x + threadIdx.x;
    int stride = gridDim.x * blockDim.x;
    for (int e = i; e < NUM_E; e += stride) {
        int src = ei[e];
        int dst = ei[NUM_E + e];
        int p = atomicAdd(&g_cursor[dst], 1);
        g_csr[p] = src;
    }
}
__global__ void invdeg_kernel() {
    int i = blockIdx.x * blockDim.x + threadIdx.x;
    int stride = gridDim.x * blockDim.x;
    for (int idx = i; idx < N_NODES; idx += stride)
        g_invdeg[idx] = 1.0f / fmaxf((float)g_deg[idx], 1.0f);
}

// ---------------- projection (tf32 mma, persistent): h = relu(x @ W + b) ----------------
__global__ void __launch_bounds__(256) proj_kernel(const float* __restrict__ x,
                                                   const float* __restrict__ w,
                                                   const float* __restrict__ b) {
    __shared__ float sB[64 * 136];
    __shared__ float sbias[128];
    int tid = threadIdx.x, lane = tid & 31, warp = tid >> 5;
    int tg = lane & 3, g = lane >> 2;
    for (int i = tid; i < 64 * 32; i += 256) {
        int r = i >> 5, c4 = (i & 31) * 4;
        float4 v = *(const float4*)(w + r * HDIM + c4);
        float* d = &sB[r * 136 + c4];
        d[0] = tf32f(v.x); d[1] = tf32f(v.y); d[2] = tf32f(v.z); d[3] = tf32f(v.w);
    }
    if (tid < 128) sbias[tid] = b[tid];
    __syncthreads();

    for (int tile = blockIdx.x; tile < NTILES; tile += gridDim.x) {
        int grow0 = tile * 128 + warp * 16 + g;
        int grow1 = grow0 + 8;
        bool v0 = grow0 < N_NODES, v1 = grow1 < N_NODES;
        const float* r0 = x + (size_t)grow0 * DIM_IN;
        const float* r1 = x + (size_t)grow1 * DIM_IN;

        float acc[16][4];
#pragma unroll
        for (int t = 0; t < 16; t++) { acc[t][0]=0.f; acc[t][1]=0.f; acc[t][2]=0.f; acc[t][3]=0.f; }

        unsigned A0[4], A1[4];
        auto ldfrag = [&](unsigned* A, int s) {
            int kk = s * 8;
            A[0]=0u; A[1]=0u; A[2]=0u; A[3]=0u;
            if (v0) { A[0]=tf32u(r0[kk+tg]); A[2]=tf32u(r0[kk+tg+4]); }
            if (v1) { A[1]=tf32u(r1[kk+tg]); A[3]=tf32u(r1[kk+tg+4]); }
        };
        ldfrag(A0, 0); ldfrag(A1, 1);
#pragma unroll
        for (int s = 0; s < 8; s += 2) {
            const float* bb = &sB[(s * 8 + tg) * 136 + g];
#pragma unroll
            for (int t = 0; t < 16; t++) {
                unsigned b0 = __float_as_uint(bb[t * 8]);
                unsigned b1 = __float_as_uint(bb[t * 8 + 544]);
                mma_tf32(acc[t][0], acc[t][1], acc[t][2], acc[t][3],
                         A0[0], A0[1], A0[2], A0[3], b0, b1);
            }
            if (s + 2 < 8) ldfrag(A0, s + 2);
            const float* bb1 = &sB[((s + 1) * 8 + tg) * 136 + g];
#pragma unroll
            for (int t = 0; t < 16; t++) {
                unsigned b0 = __float_as_uint(bb1[t * 8]);
                unsigned b1 = __float_as_uint(bb1[t * 8 + 544]);
                mma_tf32(acc[t][0], acc[t][1], acc[t][2], acc[t][3],
                         A1[0], A1[1], A1[2], A1[3], b0, b1);
            }
            if (s + 3 < 8) ldfrag(A1, s + 3);
        }
        if (v0) {
#pragma unroll
            for (int t = 0; t < 16; t++) {
                int c = t * 8 + tg * 2;
                float2 o = make_float2(fmaxf(acc[t][0] + sbias[c], 0.f),
                                       fmaxf(acc[t][1] + sbias[c + 1], 0.f));
                *(float2*)(g_h + (size_t)grow0 * HDIM + c) = o;
            }
        }
        if (v1) {
#pragma unroll
            for (int t = 0; t < 16; t++) {
                int c = t * 8 + tg * 2;
                float2 o = make_float2(fmaxf(acc[t][2] + sbias[c], 0.f),
                                       fmaxf(acc[t][3] + sbias[c + 1], 0.f));
                *(float2*)(g_h + (size_t)grow1 * HDIM + c) = o;
            }
        }
    }
}

// ---------------- aggregation: warp-per-node CSR gather ----------------
__global__ void __launch_bounds__(256) aggregate_kernel() {
    int gw = (blockIdx.x * blockDim.x + threadIdx.x) >> 5;
    int lane = threadIdx.x & 31;
    int nw = (gridDim.x * blockDim.x) >> 5;
    for (int v = gw; v < N_NODES; v += nw) {
        int beg = g_off[v], end = g_off[v + 1];
        float x0 = 0.f, x1 = 0.f, x2 = 0.f, x3 = 0.f;
        int e = beg;
        for (; e + 4 <= end; e += 4) {
            int s0 = g_csr[e], s1 = g_csr[e + 1], s2 = g_csr[e + 2], s3 = g_csr[e + 3];
            float4 u0 = *((const float4*)(g_h + (size_t)s0 * HDIM) + lane);
            float4 u1 = *((const float4*)(g_h + (size_t)s1 * HDIM) + lane);
            float4 u2 = *((const float4*)(g_h + (size_t)s2 * HDIM) + lane);
            float4 u3 = *((const float4*)(g_h + (size_t)s3 * HDIM) + lane);
            x0 += (u0.x + u1.x) + (u2.x + u3.x);
            x1 += (u0.y + u1.y) + (u2.y + u3.y);
            x2 += (u0.z + u1.z) + (u2.z + u3.z);
            x3 += (u0.w + u1.w) + (u2.w + u3.w);
        }
        for (; e < end; e++) {
            int s0 = g_csr[e];
            float4 u = *((const float4*)(g_h + (size_t)s0 * HDIM) + lane);
            x0 += u.x; x1 += u.y; x2 += u.z; x3 += u.w;
        }
        float inv = g_invdeg[v];
        float4 o = make_float4(x0 * inv, x1 * inv, x2 * inv, x3 * inv);
        *((float4*)(g_aggr + (size_t)v * HDIM) + lane) = o;
    }
}

// ---------------- fused layer (persistent tf32 mma, K=256, whole B in smem) ----------------
__global__ void __launch_bounds__(256) layer_kernel(const float* __restrict__ wl,
                                                    const float* __restrict__ bl,
                                                    const float* __restrict__ wr,
                                                    const float* __restrict__ lg,
                                                    const float* __restrict__ lb) {
    extern __shared__ float sB[];   // [256][136] tf32
    __shared__ float sGB[384];
    int tid = threadIdx.x, lane = tid & 31, warp = tid >> 5;
    int tg = lane & 3, g = lane >> 2;
    if (tid < 128) { sGB[tid] = lg[tid]; sGB[128 + tid] = lb[tid]; sGB[256 + tid] = bl[tid]; }
    for (int i = tid; i < 256 * 32; i += 256) {
        int r = i >> 5, c4 = (i & 31) * 4;
        const float* src = (r < 128) ? (wl + r * HDIM + c4) : (wr + (r - 128) * HDIM + c4);
        float4 v = *(const float4*)src;
        float* d = &sB[r * 136 + c4];
        d[0] = tf32f(v.x); d[1] = tf32f(v.y); d[2] = tf32f(v.z); d[3] = tf32f(v.w);
    }
    __syncthreads();

    for (int tile = blockIdx.x; tile < NTILES; tile += gridDim.x) {
        int grow0 = tile * 128 + warp * 16 + g;
        int grow1 = grow0 + 8;
        bool v0 = grow0 < N_NODES, v1 = grow1 < N_NODES;
        const float* r0a = g_aggr + (size_t)grow0 * HDIM;
        const float* r1a = g_aggr + (size_t)grow1 * HDIM;
        const float* r0h = g_h + (size_t)grow0 * HDIM;
        const float* r1h = g_h + (size_t)grow1 * HDIM;

        float acc[16][4];
#pragma unroll
        for (int t = 0; t < 16; t++) { acc[t][0]=0.f; acc[t][1]=0.f; acc[t][2]=0.f; acc[t][3]=0.f; }

        unsigned A0[4], A1[4];
        auto ldfrag = [&](unsigned* A, int s) {
            int kk = s * 8;
            const float* p0 = (kk < HDIM) ? (r0a + kk) : (r0h + kk - HDIM);
            const float* p1 = (kk < HDIM) ? (r1a + kk) : (r1h + kk - HDIM);
            A[0]=0u; A[1]=0u; A[2]=0u; A[3]=0u;
            if (v0) { A[0]=tf32u(p0[tg]); A[2]=tf32u(p0[tg+4]); }
            if (v1) { A[1]=tf32u(p1[tg]); A[3]=tf32u(p1[tg+4]); }
        };
        ldfrag(A0, 0); ldfrag(A1, 1);
#pragma unroll
        for (int s = 0; s < 32; s += 2) {
            const float* bb = &sB[(s * 8 + tg) * 136 + g];
#pragma unroll
            for (int t = 0; t < 16; t++) {
                unsigned b0 = __float_as_uint(bb[t * 8]);
                unsigned b1 = __float_as_uint(bb[t * 8 + 544]);
                mma_tf32(acc[t][0], acc[t][1], acc[t][2], acc[t][3],
                         A0[0], A0[1], A0[2], A0[3], b0, b1);
            }
            if (s + 2 < 32) ldfrag(A0, s + 2);
            const float* bb1 = &sB[((s + 1) * 8 + tg) * 136 + g];
#pragma unroll
            for (int t = 0; t < 16; t++) {
                unsigned b0 = __float_as_uint(bb1[t * 8]);
                unsigned b1 = __float_as_uint(bb1[t * 8 + 544]);
                mma_tf32(acc[t][0], acc[t][1], acc[t][2], acc[t][3],
                         A1[0], A1[1], A1[2], A1[3], b0, b1);
            }
            if (s + 3 < 32) ldfrag(A1, s + 3);
        }

        // epilogue: bias, LN, ELU, residual
        float s0 = 0.f, q0 = 0.f, s1 = 0.f, q1 = 0.f;
#pragma unroll
        for (int t = 0; t < 16; t++) {
            int c = t * 8 + tg * 2;
            float bb0 = sGB[256 + c], bb1 = sGB[256 + c + 1];
            acc[t][0] += bb0; acc[t][1] += bb1; acc[t][2] += bb0; acc[t][3] += bb1;
            s0 += acc[t][0] + acc[t][1]; q0 += acc[t][0]*acc[t][0] + acc[t][1]*acc[t][1];
            s1 += acc[t][2] + acc[t][3]; q1 += acc[t][2]*acc[t][2] + acc[t][3]*acc[t][3];
        }
#pragma unroll
        for (int o = 1; o <= 2; o <<= 1) {
            s0 += __shfl_xor_sync(0xffffffffu, s0, o);
            q0 += __shfl_xor_sync(0xffffffffu, q0, o);
            s1 += __shfl_xor_sync(0xffffffffu, s1, o);
            q1 += __shfl_xor_sync(0xffffffffu, q1, o);
        }
        float mu0 = s0 * (1.0f / HDIM), mu1 = s1 * (1.0f / HDIM);
        float rs0 = rsqrtf(q0 * (1.0f / HDIM) - mu0 * mu0 + LN_EPS);
        float rs1 = rsqrtf(q1 * (1.0f / HDIM) - mu1 * mu1 + LN_EPS);
        if (v0) {
#pragma unroll
            for (int t = 0; t < 16; t++) {
                int c = t * 8 + tg * 2;
                float n0 = (acc[t][0] - mu0) * rs0 * sGB[c] + sGB[128 + c];
                float n1 = (acc[t][1] - mu0) * rs0 * sGB[c + 1] + sGB[128 + c + 1];
                float e0 = n0 > 0.f ? n0 : expm1f(n0);
                float e1 = n1 > 0.f ? n1 : expm1f(n1);
                float* hp = g_h + (size_t)grow0 * HDIM + c;
                float2 o = make_float2(e0 + hp[0], e1 + hp[1]);
                *(float2*)hp = o;
            }
        }
        if (v1) {
#pragma unroll
            for (int t = 0; t < 16; t++) {
                int c = t * 8 + tg * 2;
                float n0 = (acc[t][2] - mu1) * rs1 * sGB[c] + sGB[128 + c];
                float n1 = (acc[t][3] - mu1) * rs1 * sGB[c + 1] + sGB[128 + c + 1];
                float e0 = n0 > 0.f ? n0 : expm1f(n0);
                float e1 = n1 > 0.f ? n1 : expm1f(n1);
                float* hp = g_h + (size_t)grow1 * HDIM + c;
                float2 o = make_float2(e0 + hp[0], e1 + hp[1]);
                *(float2*)hp = o;
            }
        }
    }
}

// ---------------- gate (tf32 mma FC1 + fused FC2 + segment max) ----------------
__global__ void __launch_bounds__(256) gate_kernel(const float* __restrict__ gw1,
                                                   const float* __restrict__ gb1,
                                                   const float* __restrict__ gw2,
                                                   const float* __restrict__ gb2,
                                                   const int* __restrict__ batch) {
    __shared__ float sB[128 * 72];
    __shared__ float sb1[64], sw2[64];
    __shared__ float sb2s;
    int tid = threadIdx.x, lane = tid & 31, warp = tid >> 5;
    int tg = lane & 3, g = lane >> 2;
    for (int i = tid; i < 128 * 16; i += 256) {
        int r = i >> 4, c4 = (i & 15) * 4;
        float4 v = *(const float4*)(gw1 + r * 64 + c4);
        float* d = &sB[r * 72 + c4];
        d[0] = tf32f(v.x); d[1] = tf32f(v.y); d[2] = tf32f(v.z); d[3] = tf32f(v.w);
    }
    if (tid < 64) { sb1[tid] = gb1[tid]; sw2[tid] = gw2[tid]; }
    if (tid == 0) sb2s = gb2[0];
    __syncthreads();

    for (int tile = blockIdx.x; tile < NTILES; tile += gridDim.x) {
        int grow0 = tile * 128 + warp * 16 + g;
        int grow1 = grow0 + 8;
        bool v0 = grow0 < N_NODES, v1 = grow1 < N_NODES;
        const float* r0 = g_h + (size_t)grow0 * HDIM;
        const float* r1 = g_h + (size_t)grow1 * HDIM;

        float acc[8][4];
#pragma unroll
        for (int t = 0; t < 8; t++) { acc[t][0]=0.f; acc[t][1]=0.f; acc[t][2]=0.f; acc[t][3]=0.f; }

        unsigned A0[4], A1[4];
        auto ldfrag = [&](unsigned* A, int s) {
            int kk = s * 8;
            A[0]=0u; A[1]=0u; A[2]=0u; A[3]=0u;
            if (v0) { A[0]=tf32u(r0[kk+tg]); A[2]=tf32u(r0[kk+tg+4]); }
            if (v1) { A[1]=tf32u(r1[kk+tg]); A[3]=tf32u(r1[kk+tg+4]); }
        };
        ldfrag(A0, 0); ldfrag(A1, 1);
#pragma unroll
        for (int s = 0; s < 16; s += 2) {
            const float* bb = &sB[(s * 8 + tg) * 72 + g];
#pragma unroll
            for (int t = 0; t < 8; t++) {
                unsigned b0 = __float_as_uint(bb[t * 8]);
                unsigned b1 = __float_as_uint(bb[t * 8 + 288]);
                mma_tf32(acc[t][0], acc[t][1], acc[t][2], acc[t][3],
                         A0[0], A0[1], A0[2], A0[3], b0, b1);
            }
            if (s + 2 < 16) ldfrag(A0, s + 2);
            const float* bb1 = &sB[((s + 1) * 8 + tg) * 72 + g];
#pragma unroll
            for (int t = 0; t < 8; t++) {
                unsigned b0 = __float_as_uint(bb1[t * 8]);
                unsigned b1 = __float_as_uint(bb1[t * 8 + 288]);
                mma_tf32(acc[t][0], acc[t][1], acc[t][2], acc[t][3],
                         A1[0], A1[1], A1[2], A1[3], b0, b1);
            }
            if (s + 3 < 16) ldfrag(A1, s + 3);
        }
        // epilogue: relu(acc+b1) dot w2 per row
        float rr0 = 0.f, rr1 = 0.f;
#pragma unroll
        for (int t = 0; t < 8; t++) {
            int c = t * 8 + tg * 2;
            rr0 += fmaxf(acc[t][0] + sb1[c], 0.f) * sw2[c]
                 + fmaxf(acc[t][1] + sb1[c + 1], 0.f) * sw2[c + 1];
            rr1 += fmaxf(acc[t][2] + sb1[c], 0.f) * sw2[c]
                 + fmaxf(acc[t][3] + sb1[c + 1], 0.f) * sw2[c + 1];
        }
#pragma unroll
        for (int o = 1; o <= 2; o <<= 1) {
            rr0 += __shfl_xor_sync(0xffffffffu, rr0, o);
            rr1 += __shfl_xor_sync(0xffffffffu, rr1, o);
        }
        if (tg == 0) {
            if (v0) {
                float gv = rr0 + sb2s;
                g_gate[grow0] = gv;
                atomicMax(&g_gmax_ord[batch[grow0]], float_to_ord(gv));
            }
            if (v1) {
                float gv = rr1 + sb2s;
                g_gate[grow1] = gv;
                atomicMax(&g_gmax_ord[batch[grow1]], float_to_ord(gv));
            }
        }
    }
}

// ---------------- softmax pieces ----------------
__global__ void eg_kernel(const int* __restrict__ batch) {
    int i = blockIdx.x * blockDim.x + threadIdx.x;
    int stride = gridDim.x * blockDim.x;
    for (int idx = i; idx < N_NODES; idx += stride) {
        int b = batch[idx];
        float m = ord_to_float(g_gmax_ord[b]);
        float e = expf(g_gate[idx] - m);
        g_gate[idx] = e;
        atomicAdd(&g_gsum[b], e);
    }
}
__device__ __forceinline__ void red_add_v4(float* addr, float a, float b, float c, float d) {
    asm volatile("red.global.add.v4.f32 [%0], {%1,%2,%3,%4};"
                 :: "l"(addr), "f"(a), "f"(b), "f"(c), "f"(d) : "memory");
}
__global__ void __launch_bounds__(256) pooled_kernel(const int* __restrict__ batch) {
    int gw = (blockIdx.x * blockDim.x + threadIdx.x) >> 5;
    int lane = threadIdx.x & 31;
    int nw = (gridDim.x * blockDim.x) >> 5;
    for (int row = gw; row < N_NODES; row += nw) {
        int b = batch[row];
        float alpha = g_gate[row] / g_gsum[b];
        const float4 v = *((const float4*)(g_h + (size_t)row * HDIM) + lane);
        red_add_v4(g_pooled + (size_t)b * HDIM + lane * 4,
                   v.x * alpha, v.y * alpha, v.z * alpha, v.w * alpha);
    }
}
__global__ void __launch_bounds__(64) cls_kernel(const float* __restrict__ w1,
                                                 const float* __restrict__ b1,
                                                 const float* __restrict__ w2,
                                                 const float* __restrict__ b2,
                                                 float* __restrict__ out) {
    int gidx = blockIdx.x;
    int j = threadIdx.x;
    __shared__ float sp[HDIM];
    __shared__ float shid[64];
    sp[j] = g_pooled[(size_t)gidx * HDIM + j];
    sp[j + 64] = g_pooled[(size_t)gidx * HDIM + j + 64];
    __syncthreads();
    float acc = b1[j];
#pragma unroll
    for (int k = 0; k < HDIM; k++) acc += sp[k] * w1[k * 64 + j];
    shid[j] = fmaxf(acc, 0.f);
    __syncthreads();
    if (j < NCLASSES) {
        float o = b2[j];
#pragma unroll
        for (int k = 0; k < 64; k++) o += shid[k] * w2[k * NCLASSES + j];
        out[(size_t)gidx * NCLASSES + j] = o;
    }
}

// ---------------- launch ----------------
extern "C" void kernel_launch(void* const* d_in, const int* in_sizes, int n_in,
                              void* d_out, int out_size) {
    const float* x       = (const float*)d_in[0];
    const int*   ei      = (const int*)d_in[1];
    const int*   batch   = (const int*)d_in[2];
    const float* proj_w  = (const float*)d_in[3];
    const float* proj_b  = (const float*)d_in[4];
    const float* lin_l_w = (const float*)d_in[5];
    const float* lin_l_b = (const float*)d_in[6];
    const float* lin_r_w = (const float*)d_in[7];
    const float* ln_g    = (const float*)d_in[8];
    const float* ln_b    = (const float*)d_in[9];
    const float* gate_w1 = (const float*)d_in[10];
    const float* gate_b1 = (const float*)d_in[11];
    const float* gate_w2 = (const float*)d_in[12];
    const float* gate_b2 = (const float*)d_in[13];
    const float* cls_w1  = (const float*)d_in[14];
    const float* cls_b1  = (const float*)d_in[15];
    const float* cls_w2  = (const float*)d_in[16];
    const float* cls_b2  = (const float*)d_in[17];
    float* out = (float*)d_out;

    const int LAYER_SMEM = 256 * 136 * 4;
    cudaFuncSetAttribute(layer_kernel, cudaFuncAttributeMaxDynamicSharedMemorySize, LAYER_SMEM);

    init_kernel<<<512, 256>>>();
    deg_kernel<<<2048, 256>>>(ei);
    scan_a_kernel<<<NBLK, 1024>>>();
    scan_b_kernel<<<1, 128>>>();
    scan_c_kernel<<<NBLK, 1024>>>();
    fill_kernel<<<2048, 256>>>(ei);
    invdeg_kernel<<<392, 256>>>();
    proj_kernel<<<296, 256>>>(x, proj_w, proj_b);

    for (int l = 0; l < NLAYERS; l++) {
        aggregate_kernel<<<2048, 256>>>();
        layer_kernel<<<148, 256, LAYER_SMEM>>>(lin_l_w + (size_t)l * HDIM * HDIM,
                                               lin_l_b + (size_t)l * HDIM,
                                               lin_r_w + (size_t)l * HDIM * HDIM,
                                               ln_g + (size_t)l * HDIM,
                                               ln_b + (size_t)l * HDIM);
    }

    gate_kernel<<<296, 256>>>(gate_w1, gate_b1, gate_w2, gate_b2, batch);
    eg_kernel<<<392, 256>>>(batch);
    pooled_kernel<<<2048, 256>>>(batch);
    cls_kernel<<<NGRAPHS, 64>>>(cls_w1, cls_b1, cls_w2, cls_b2, out);
}

// round 4
// speedup vs baseline: 4.3070x; 1.0039x over previous
#include <cuda_runtime.h>
#include <cuda_bf16.h>
#include <cstdint>

#define N_NODES   100000
#define NUM_E     1600000
#define DIM_IN    64
#define HDIM      128
#define NLAYERS   3
#define NGRAPHS   512
#define NCLASSES  6
#define LN_EPS    1e-5f
#define NBLK      98
#define NTILES    782          // ceil(100000/128)

// ---------------- scratch ----------------
__device__ float         g_h[(size_t)N_NODES * HDIM];
__device__ __nv_bfloat162 g_hbf[(size_t)N_NODES * HDIM / 2];   // bf16 shadow of g_h
__device__ float         g_aggr[(size_t)N_NODES * HDIM];
__device__ float         g_invdeg[N_NODES];
__device__ int           g_deg[N_NODES];
__device__ int           g_off[N_NODES + 1];
__device__ int           g_cursor[N_NODES];
__device__ int           g_csr[NUM_E];
__device__ int           g_bsum[NBLK];
__device__ int           g_boff[NBLK];
__device__ float         g_gate[N_NODES];
__device__ unsigned      g_gmax_ord[NGRAPHS];
__device__ float         g_gsum[NGRAPHS];
__device__ float         g_pooled[NGRAPHS * HDIM];

// ---------------- helpers ----------------
__device__ __forceinline__ unsigned float_to_ord(float f) {
    unsigned u = __float_as_uint(f);
    return (u & 0x80000000u) ? ~u : (u | 0x80000000u);
}
__device__ __forceinline__ float ord_to_float(unsigned u) {
    return __uint_as_float((u & 0x80000000u) ? (u & 0x7fffffffu) : ~u);
}
__device__ __forceinline__ unsigned tf32u(float x) {
    unsigned r; asm("cvt.rna.tf32.f32 %0, %1;" : "=r"(r) : "f"(x)); return r;
}
__device__ __forceinline__ float tf32f(float x) {
    float r; asm("cvt.rna.tf32.f32 %0, %1;" : "=f"(r) : "f"(x)); return r;
}
__device__ __forceinline__ void mma_tf32(float& d0, float& d1, float& d2, float& d3,
                                         unsigned a0, unsigned a1, unsigned a2, unsigned a3,
                                         unsigned b0, unsigned b1) {
    asm volatile("mma.sync.aligned.m16n8k8.row.col.f32.tf32.tf32.f32 "
                 "{%0,%1,%2,%3},{%4,%5,%6,%7},{%8,%9},{%0,%1,%2,%3};"
                 : "+f"(d0), "+f"(d1), "+f"(d2), "+f"(d3)
                 : "r"(a0), "r"(a1), "r"(a2), "r"(a3), "r"(b0), "r"(b1));
}
// unpack packed bf16x2 (as uint) into two floats via bit ops
__device__ __forceinline__ void bf2f(unsigned u, float& lo, float& hi) {
    lo = __uint_as_float(u << 16);
    hi = __uint_as_float(u & 0xffff0000u);
}
__device__ __forceinline__ void store_h_pair(int row, int c, float a, float b) {
    *(float2*)(g_h + (size_t)row * HDIM + c) = make_float2(a, b);
    g_hbf[((size_t)row * HDIM + c) >> 1] = __floats2bfloat162_rn(a, b);
}

// ---------------- init / degree / CSR ----------------
__global__ void init_kernel() {
    int i = blockIdx.x * blockDim.x + threadIdx.x;
    int stride = gridDim.x * blockDim.x;
    for (int idx = i; idx < N_NODES; idx += stride) g_deg[idx] = 0;
    for (int idx = i; idx < NGRAPHS; idx += stride) { g_gmax_ord[idx] = 0u; g_gsum[idx] = 0.0f; }
    for (int idx = i; idx < NGRAPHS * HDIM; idx += stride) g_pooled[idx] = 0.0f;
}
__global__ void deg_kernel(const int* __restrict__ ei) {
    int i = blockIdx.x * blockDim.x + threadIdx.x;
    int stride = gridDim.x * blockDim.x;
    for (int e = i; e < NUM_E; e += stride) atomicAdd(&g_deg[ei[NUM_E + e]], 1);
}
__global__ void __launch_bounds__(1024) scan_a_kernel() {
    int i = blockIdx.x * 1024 + threadIdx.x;
    int lane = threadIdx.x & 31;
    int v = (i < N_NODES) ? g_deg[i] : 0;
#pragma unroll
    for (int o = 16; o; o >>= 1) v += __shfl_xor_sync(0xffffffffu, v, o);
    __shared__ int wsum[32];
    if (lane == 0) wsum[threadIdx.x >> 5] = v;
    __syncthreads();
    if (threadIdx.x < 32) {
        int t = wsum[threadIdx.x];
#pragma unroll
        for (int o = 16; o; o >>= 1) t += __shfl_xor_sync(0xffffffffu, t, o);
        if (threadIdx.x == 0) g_bsum[blockIdx.x] = t;
    }
}
__global__ void __launch_bounds__(128) scan_b_kernel() {
    __shared__ int sm[128];
    int t = threadIdx.x;
    int v = (t < NBLK) ? g_bsum[t] : 0;
    sm[t] = v; __syncthreads();
    for (int o = 1; o < 128; o <<= 1) {
        int tmp = (t >= o) ? sm[t - o] : 0;
        __syncthreads();
        sm[t] += tmp;
        __syncthreads();
    }
    if (t < NBLK) g_boff[t] = sm[t] - v;
    if (t == NBLK - 1) g_off[N_NODES] = sm[t];
}
__global__ void __launch_bounds__(1024) scan_c_kernel() {
    __shared__ int sm[1024];
    int t = threadIdx.x;
    int i = blockIdx.x * 1024 + t;
    int v = (i < N_NODES) ? g_deg[i] : 0;
    sm[t] = v; __syncthreads();
    for (int o = 1; o < 1024; o <<= 1) {
        int tmp = (t >= o) ? sm[t - o] : 0;
        __syncthreads();
        sm[t] += tmp;
        __syncthreads();
    }
    if (i < N_NODES) {
        int off = g_boff[blockIdx.x] + sm[t] - v;
        g_off[i] = off;
        g_cursor[i] = off;
        g_invdeg[i] = 1.0f / fmaxf((float)v, 1.0f);
    }
}
__global__ void fill_kernel(const int* __restrict__ ei) {
    int i = blockIdx.x * blockDim.x + threadIdx.x;
    int stride = gridDim.x * blockDim.x;
    for (int e = i; e < NUM_E; e += stride) {
        int src = ei[e];
        int dst = ei[NUM_E + e];
        int p = atomicAdd(&g_cursor[dst], 1);
        g_csr[p] = src;
    }
}

// ---------------- projection (tf32 mma, persistent): h = relu(x @ W + b) ----------------
__global__ void __launch_bounds__(256) proj_kernel(const float* __restrict__ x,
                                                   const float* __restrict__ w,
                                                   const float* __restrict__ b) {
    __shared__ float sB[64 * 136];
    __shared__ float sbias[128];
    int tid = threadIdx.x, lane = tid & 31, warp = tid >> 5;
    int tg = lane & 3, g = lane >> 2;
    for (int i = tid; i < 64 * 32; i += 256) {
        int r = i >> 5, c4 = (i & 31) * 4;
        float4 v = *(const float4*)(w + r * HDIM + c4);
        float* d = &sB[r * 136 + c4];
        d[0] = tf32f(v.x); d[1] = tf32f(v.y); d[2] = tf32f(v.z); d[3] = tf32f(v.w);
    }
    if (tid < 128) sbias[tid] = b[tid];
    __syncthreads();

    for (int tile = blockIdx.x; tile < NTILES; tile += gridDim.x) {
        int grow0 = tile * 128 + warp * 16 + g;
        int grow1 = grow0 + 8;
        bool v0 = grow0 < N_NODES, v1 = grow1 < N_NODES;
        const float* r0 = x + (size_t)grow0 * DIM_IN;
        const float* r1 = x + (size_t)grow1 * DIM_IN;

        float acc[16][4];
#pragma unroll
        for (int t = 0; t < 16; t++) { acc[t][0]=0.f; acc[t][1]=0.f; acc[t][2]=0.f; acc[t][3]=0.f; }

        unsigned A0[4], A1[4];
        auto ldfrag = [&](unsigned* A, int s) {
            int kk = s * 8;
            A[0]=0u; A[1]=0u; A[2]=0u; A[3]=0u;
            if (v0) { A[0]=tf32u(r0[kk+tg]); A[2]=tf32u(r0[kk+tg+4]); }
            if (v1) { A[1]=tf32u(r1[kk+tg]); A[3]=tf32u(r1[kk+tg+4]); }
        };
        ldfrag(A0, 0); ldfrag(A1, 1);
#pragma unroll
        for (int s = 0; s < 8; s += 2) {
            const float* bb = &sB[(s * 8 + tg) * 136 + g];
#pragma unroll
            for (int t = 0; t < 16; t++) {
                unsigned b0 = __float_as_uint(bb[t * 8]);
                unsigned b1 = __float_as_uint(bb[t * 8 + 544]);
                mma_tf32(acc[t][0], acc[t][1], acc[t][2], acc[t][3],
                         A0[0], A0[1], A0[2], A0[3], b0, b1);
            }
            if (s + 2 < 8) ldfrag(A0, s + 2);
            const float* bb1 = &sB[((s + 1) * 8 + tg) * 136 + g];
#pragma unroll
            for (int t = 0; t < 16; t++) {
                unsigned b0 = __float_as_uint(bb1[t * 8]);
                unsigned b1 = __float_as_uint(bb1[t * 8 + 544]);
                mma_tf32(acc[t][0], acc[t][1], acc[t][2], acc[t][3],
                         A1[0], A1[1], A1[2], A1[3], b0, b1);
            }
            if (s + 3 < 8) ldfrag(A1, s + 3);
        }
        if (v0) {
#pragma unroll
            for (int t = 0; t < 16; t++) {
                int c = t * 8 + tg * 2;
                store_h_pair(grow0, c, fmaxf(acc[t][0] + sbias[c], 0.f),
                                       fmaxf(acc[t][1] + sbias[c + 1], 0.f));
            }
        }
        if (v1) {
#pragma unroll
            for (int t = 0; t < 16; t++) {
                int c = t * 8 + tg * 2;
                store_h_pair(grow1, c, fmaxf(acc[t][2] + sbias[c], 0.f),
                                       fmaxf(acc[t][3] + sbias[c + 1], 0.f));
            }
        }
    }
}

// ---------------- aggregation: warp-per-node CSR gather over bf16 shadow ----------------
__global__ void __launch_bounds__(256) aggregate_kernel() {
    int gw = (blockIdx.x * blockDim.x + threadIdx.x) >> 5;
    int lane = threadIdx.x & 31;
    int nw = (gridDim.x * blockDim.x) >> 5;
    const uint2* hb = reinterpret_cast<const uint2*>(g_hbf);   // 8B = 4 bf16 per lane
    for (int v = gw; v < N_NODES; v += nw) {
        int beg = g_off[v], end = g_off[v + 1];
        float x0 = 0.f, x1 = 0.f, x2 = 0.f, x3 = 0.f;
        int e = beg;
        for (; e + 4 <= end; e += 4) {
            int s0 = g_csr[e], s1 = g_csr[e + 1], s2 = g_csr[e + 2], s3 = g_csr[e + 3];
            uint2 u0 = hb[(size_t)s0 * 32 + lane];
            uint2 u1 = hb[(size_t)s1 * 32 + lane];
            uint2 u2 = hb[(size_t)s2 * 32 + lane];
            uint2 u3 = hb[(size_t)s3 * 32 + lane];
            float a, b;
            bf2f(u0.x, a, b); x0 += a; x1 += b;
            bf2f(u0.y, a, b); x2 += a; x3 += b;
            bf2f(u1.x, a, b); x0 += a; x1 += b;
            bf2f(u1.y, a, b); x2 += a; x3 += b;
            bf2f(u2.x, a, b); x0 += a; x1 += b;
            bf2f(u2.y, a, b); x2 += a; x3 += b;
            bf2f(u3.x, a, b); x0 += a; x1 += b;
            bf2f(u3.y, a, b); x2 += a; x3 += b;
        }
        for (; e < end; e++) {
            int s0 = g_csr[e];
            uint2 u = hb[(size_t)s0 * 32 + lane];
            float a, b;
            bf2f(u.x, a, b); x0 += a; x1 += b;
            bf2f(u.y, a, b); x2 += a; x3 += b;
        }
        float inv = g_invdeg[v];
        float4 o = make_float4(x0 * inv, x1 * inv, x2 * inv, x3 * inv);
        *((float4*)(g_aggr + (size_t)v * HDIM) + lane) = o;
    }
}

// ---------------- fused layer (persistent tf32 mma, K=256, whole B in smem) ----------------
__global__ void __launch_bounds__(256) layer_kernel(const float* __restrict__ wl,
                                                    const float* __restrict__ bl,
                                                    const float* __restrict__ wr,
                                                    const float* __restrict__ lg,
                                                    const float* __restrict__ lb) {
    extern __shared__ float sB[];   // [256][136] tf32
    __shared__ float sGB[384];
    int tid = threadIdx.x, lane = tid & 31, warp = tid >> 5;
    int tg = lane & 3, g = lane >> 2;
    if (tid < 128) { sGB[tid] = lg[tid]; sGB[128 + tid] = lb[tid]; sGB[256 + tid] = bl[tid]; }
    for (int i = tid; i < 256 * 32; i += 256) {
        int r = i >> 5, c4 = (i & 31) * 4;
        const float* src = (r < 128) ? (wl + r * HDIM + c4) : (wr + (r - 128) * HDIM + c4);
        float4 v = *(const float4*)src;
        float* d = &sB[r * 136 + c4];
        d[0] = tf32f(v.x); d[1] = tf32f(v.y); d[2] = tf32f(v.z); d[3] = tf32f(v.w);
    }
    __syncthreads();

    for (int tile = blockIdx.x; tile < NTILES; tile += gridDim.x) {
        int grow0 = tile * 128 + warp * 16 + g;
        int grow1 = grow0 + 8;
        bool v0 = grow0 < N_NODES, v1 = grow1 < N_NODES;
        const float* r0a = g_aggr + (size_t)grow0 * HDIM;
        const float* r1a = g_aggr + (size_t)grow1 * HDIM;
        const float* r0h = g_h + (size_t)grow0 * HDIM;
        const float* r1h = g_h + (size_t)grow1 * HDIM;

        float acc[16][4];
#pragma unroll
        for (int t = 0; t < 16; t++) { acc[t][0]=0.f; acc[t][1]=0.f; acc[t][2]=0.f; acc[t][3]=0.f; }

        unsigned A0[4], A1[4];
        auto ldfrag = [&](unsigned* A, int s) {
            int kk = s * 8;
            const float* p0 = (kk < HDIM) ? (r0a + kk) : (r0h + kk - HDIM);
            const float* p1 = (kk < HDIM) ? (r1a + kk) : (r1h + kk - HDIM);
            A[0]=0u; A[1]=0u; A[2]=0u; A[3]=0u;
            if (v0) { A[0]=tf32u(p0[tg]); A[2]=tf32u(p0[tg+4]); }
            if (v1) { A[1]=tf32u(p1[tg]); A[3]=tf32u(p1[tg+4]); }
        };
        ldfrag(A0, 0); ldfrag(A1, 1);
#pragma unroll
        for (int s = 0; s < 32; s += 2) {
            const float* bb = &sB[(s * 8 + tg) * 136 + g];
#pragma unroll
            for (int t = 0; t < 16; t++) {
                unsigned b0 = __float_as_uint(bb[t * 8]);
                unsigned b1 = __float_as_uint(bb[t * 8 + 544]);
                mma_tf32(acc[t][0], acc[t][1], acc[t][2], acc[t][3],
                         A0[0], A0[1], A0[2], A0[3], b0, b1);
            }
            if (s + 2 < 32) ldfrag(A0, s + 2);
            const float* bb1 = &sB[((s + 1) * 8 + tg) * 136 + g];
#pragma unroll
            for (int t = 0; t < 16; t++) {
                unsigned b0 = __float_as_uint(bb1[t * 8]);
                unsigned b1 = __float_as_uint(bb1[t * 8 + 544]);
                mma_tf32(acc[t][0], acc[t][1], acc[t][2], acc[t][3],
                         A1[0], A1[1], A1[2], A1[3], b0, b1);
            }
            if (s + 3 < 32) ldfrag(A1, s + 3);
        }

        // epilogue: bias, LN, ELU, residual
        float s0 = 0.f, q0 = 0.f, s1 = 0.f, q1 = 0.f;
#pragma unroll
        for (int t = 0; t < 16; t++) {
            int c = t * 8 + tg * 2;
            float bb0 = sGB[256 + c], bb1 = sGB[256 + c + 1];
            acc[t][0] += bb0; acc[t][1] += bb1; acc[t][2] += bb0; acc[t][3] += bb1;
            s0 += acc[t][0] + acc[t][1]; q0 += acc[t][0]*acc[t][0] + acc[t][1]*acc[t][1];
            s1 += acc[t][2] + acc[t][3]; q1 += acc[t][2]*acc[t][2] + acc[t][3]*acc[t][3];
        }
#pragma unroll
        for (int o = 1; o <= 2; o <<= 1) {
            s0 += __shfl_xor_sync(0xffffffffu, s0, o);
            q0 += __shfl_xor_sync(0xffffffffu, q0, o);
            s1 += __shfl_xor_sync(0xffffffffu, s1, o);
            q1 += __shfl_xor_sync(0xffffffffu, q1, o);
        }
        float mu0 = s0 * (1.0f / HDIM), mu1 = s1 * (1.0f / HDIM);
        float rs0 = rsqrtf(q0 * (1.0f / HDIM) - mu0 * mu0 + LN_EPS);
        float rs1 = rsqrtf(q1 * (1.0f / HDIM) - mu1 * mu1 + LN_EPS);
        if (v0) {
#pragma unroll
            for (int t = 0; t < 16; t++) {
                int c = t * 8 + tg * 2;
                float n0 = (acc[t][0] - mu0) * rs0 * sGB[c] + sGB[128 + c];
                float n1 = (acc[t][1] - mu0) * rs0 * sGB[c + 1] + sGB[128 + c + 1];
                float e0 = n0 > 0.f ? n0 : expm1f(n0);
                float e1 = n1 > 0.f ? n1 : expm1f(n1);
                const float* hp = g_h + (size_t)grow0 * HDIM + c;
                store_h_pair(grow0, c, e0 + hp[0], e1 + hp[1]);
            }
        }
        if (v1) {
#pragma unroll
            for (int t = 0; t < 16; t++) {
                int c = t * 8 + tg * 2;
                float n0 = (acc[t][2] - mu1) * rs1 * sGB[c] + sGB[128 + c];
                float n1 = (acc[t][3] - mu1) * rs1 * sGB[c + 1] + sGB[128 + c + 1];
                float e0 = n0 > 0.f ? n0 : expm1f(n0);
                float e1 = n1 > 0.f ? n1 : expm1f(n1);
                const float* hp = g_h + (size_t)grow1 * HDIM + c;
                store_h_pair(grow1, c, e0 + hp[0], e1 + hp[1]);
            }
        }
    }
}

// ---------------- gate (tf32 mma FC1 + fused FC2 + segment max) ----------------
__global__ void __launch_bounds__(256) gate_kernel(const float* __restrict__ gw1,
                                                   const float* __restrict__ gb1,
                                                   const float* __restrict__ gw2,
                                                   const float* __restrict__ gb2,
                                                   const int* __restrict__ batch) {
    __shared__ float sB[128 * 72];
    __shared__ float sb1[64], sw2[64];
    __shared__ float sb2s;
    int tid = threadIdx.x, lane = tid & 31, warp = tid >> 5;
    int tg = lane & 3, g = lane >> 2;
    for (int i = tid; i < 128 * 16; i += 256) {
        int r = i >> 4, c4 = (i & 15) * 4;
        float4 v = *(const float4*)(gw1 + r * 64 + c4);
        float* d = &sB[r * 72 + c4];
        d[0] = tf32f(v.x); d[1] = tf32f(v.y); d[2] = tf32f(v.z); d[3] = tf32f(v.w);
    }
    if (tid < 64) { sb1[tid] = gb1[tid]; sw2[tid] = gw2[tid]; }
    if (tid == 0) sb2s = gb2[0];
    __syncthreads();

    for (int tile = blockIdx.x; tile < NTILES; tile += gridDim.x) {
        int grow0 = tile * 128 + warp * 16 + g;
        int grow1 = grow0 + 8;
        bool v0 = grow0 < N_NODES, v1 = grow1 < N_NODES;
        const float* r0 = g_h + (size_t)grow0 * HDIM;
        const float* r1 = g_h + (size_t)grow1 * HDIM;

        float acc[8][4];
#pragma unroll
        for (int t = 0; t < 8; t++) { acc[t][0]=0.f; acc[t][1]=0.f; acc[t][2]=0.f; acc[t][3]=0.f; }

        unsigned A0[4], A1[4];
        auto ldfrag = [&](unsigned* A, int s) {
            int kk = s * 8;
            A[0]=0u; A[1]=0u; A[2]=0u; A[3]=0u;
            if (v0) { A[0]=tf32u(r0[kk+tg]); A[2]=tf32u(r0[kk+tg+4]); }
            if (v1) { A[1]=tf32u(r1[kk+tg]); A[3]=tf32u(r1[kk+tg+4]); }
        };
        ldfrag(A0, 0); ldfrag(A1, 1);
#pragma unroll
        for (int s = 0; s < 16; s += 2) {
            const float* bb = &sB[(s * 8 + tg) * 72 + g];
#pragma unroll
            for (int t = 0; t < 8; t++) {
                unsigned b0 = __float_as_uint(bb[t * 8]);
                unsigned b1 = __float_as_uint(bb[t * 8 + 288]);
                mma_tf32(acc[t][0], acc[t][1], acc[t][2], acc[t][3],
                         A0[0], A0[1], A0[2], A0[3], b0, b1);
            }
            if (s + 2 < 16) ldfrag(A0, s + 2);
            const float* bb1 = &sB[((s + 1) * 8 + tg) * 72 + g];
#pragma unroll
            for (int t = 0; t < 8; t++) {
                unsigned b0 = __float_as_uint(bb1[t * 8]);
                unsigned b1 = __float_as_uint(bb1[t * 8 + 288]);
                mma_tf32(acc[t][0], acc[t][1], acc[t][2], acc[t][3],
                         A1[0], A1[1], A1[2], A1[3], b0, b1);
            }
            if (s + 3 < 16) ldfrag(A1, s + 3);
        }
        float rr0 = 0.f, rr1 = 0.f;
#pragma unroll
        for (int t = 0; t < 8; t++) {
            int c = t * 8 + tg * 2;
            rr0 += fmaxf(acc[t][0] + sb1[c], 0.f) * sw2[c]
                 + fmaxf(acc[t][1] + sb1[c + 1], 0.f) * sw2[c + 1];
            rr1 += fmaxf(acc[t][2] + sb1[c], 0.f) * sw2[c]
                 + fmaxf(acc[t][3] + sb1[c + 1], 0.f) * sw2[c + 1];
        }
#pragma unroll
        for (int o = 1; o <= 2; o <<= 1) {
            rr0 += __shfl_xor_sync(0xffffffffu, rr0, o);
            rr1 += __shfl_xor_sync(0xffffffffu, rr1, o);
        }
        if (tg == 0) {
            if (v0) {
                float gv = rr0 + sb2s;
                g_gate[grow0] = gv;
                atomicMax(&g_gmax_ord[batch[grow0]], float_to_ord(gv));
            }
            if (v1) {
                float gv = rr1 + sb2s;
                g_gate[grow1] = gv;
                atomicMax(&g_gmax_ord[batch[grow1]], float_to_ord(gv));
            }
        }
    }
}

// ---------------- softmax pieces ----------------
__global__ void eg_kernel(const int* __restrict__ batch) {
    int i = blockIdx.x * blockDim.x + threadIdx.x;
    int stride = gridDim.x * blockDim.x;
    for (int idx = i; idx < N_NODES; idx += stride) {
        int b = batch[idx];
        float m = ord_to_float(g_gmax_ord[b]);
        float e = expf(g_gate[idx] - m);
        g_gate[idx] = e;
        atomicAdd(&g_gsum[b], e);
    }
}
__device__ __forceinline__ void red_add_v4(float* addr, float a, float b, float c, float d) {
    asm volatile("red.global.add.v4.f32 [%0], {%1,%2,%3,%4};"
                 :: "l"(addr), "f"(a), "f"(b), "f"(c), "f"(d) : "memory");
}
__global__ void __launch_bounds__(256) pooled_kernel(const int* __restrict__ batch) {
    int gw = (blockIdx.x * blockDim.x + threadIdx.x) >> 5;
    int lane = threadIdx.x & 31;
    int nw = (gridDim.x * blockDim.x) >> 5;
    for (int row = gw; row < N_NODES; row += nw) {
        int b = batch[row];
        float alpha = g_gate[row] / g_gsum[b];
        const float4 v = *((const float4*)(g_h + (size_t)row * HDIM) + lane);
        red_add_v4(g_pooled + (size_t)b * HDIM + lane * 4,
                   v.x * alpha, v.y * alpha, v.z * alpha, v.w * alpha);
    }
}
__global__ void __launch_bounds__(64) cls_kernel(const float* __restrict__ w1,
                                                 const float* __restrict__ b1,
                                                 const float* __restrict__ w2,
                                                 const float* __restrict__ b2,
                                                 float* __restrict__ out) {
    int gidx = blockIdx.x;
    int j = threadIdx.x;
    __shared__ float sp[HDIM];
    __shared__ float shid[64];
    sp[j] = g_pooled[(size_t)gidx * HDIM + j];
    sp[j + 64] = g_pooled[(size_t)gidx * HDIM + j + 64];
    __syncthreads();
    float acc = b1[j];
#pragma unroll
    for (int k = 0; k < HDIM; k++) acc += sp[k] * w1[k * 64 + j];
    shid[j] = fmaxf(acc, 0.f);
    __syncthreads();
    if (j < NCLASSES) {
        float o = b2[j];
#pragma unroll
        for (int k = 0; k < 64; k++) o += shid[k] * w2[k * NCLASSES + j];
        out[(size_t)gidx * NCLASSES + j] = o;
    }
}

// ---------------- launch ----------------
extern "C" void kernel_launch(void* const* d_in, const int* in_sizes, int n_in,
                              void* d_out, int out_size) {
    const float* x       = (const float*)d_in[0];
    const int*   ei      = (const int*)d_in[1];
    const int*   batch   = (const int*)d_in[2];
    const float* proj_w  = (const float*)d_in[3];
    const float* proj_b  = (const float*)d_in[4];
    const float* lin_l_w = (const float*)d_in[5];
    const float* lin_l_b = (const float*)d_in[6];
    const float* lin_r_w = (const float*)d_in[7];
    const float* ln_g    = (const float*)d_in[8];
    const float* ln_b    = (const float*)d_in[9];
    const float* gate_w1 = (const float*)d_in[10];
    const float* gate_b1 = (const float*)d_in[11];
    const float* gate_w2 = (const float*)d_in[12];
    const float* gate_b2 = (const float*)d_in[13];
    const float* cls_w1  = (const float*)d_in[14];
    const float* cls_b1  = (const float*)d_in[15];
    const float* cls_w2  = (const float*)d_in[16];
    const float* cls_b2  = (const float*)d_in[17];
    float* out = (float*)d_out;

    const int LAYER_SMEM = 256 * 136 * 4;
    cudaFuncSetAttribute(layer_kernel, cudaFuncAttributeMaxDynamicSharedMemorySize, LAYER_SMEM);

    init_kernel<<<512, 256>>>();
    deg_kernel<<<2048, 256>>>(ei);
    scan_a_kernel<<<NBLK, 1024>>>();
    scan_b_kernel<<<1, 128>>>();
    scan_c_kernel<<<NBLK, 1024>>>();
    fill_kernel<<<2048, 256>>>(ei);
    proj_kernel<<<296, 256>>>(x, proj_w, proj_b);

    for (int l = 0; l < NLAYERS; l++) {
        aggregate_kernel<<<2048, 256>>>();
        layer_kernel<<<148, 256, LAYER_SMEM>>>(lin_l_w + (size_t)l * HDIM * HDIM,
                                               lin_l_b + (size_t)l * HDIM,
                                               lin_r_w + (size_t)l * HDIM * HDIM,
                                               ln_g + (size_t)l * HDIM,
                                               ln_b + (size_t)l * HDIM);
    }

    gate_kernel<<<296, 256>>>(gate_w1, gate_b1, gate_w2, gate_b2, batch);
    eg_kernel<<<392, 256>>>(batch);
    pooled_kernel<<<2048, 256>>>(batch);
    cls_kernel<<<NGRAPHS, 64>>>(cls_w1, cls_b1, cls_w2, cls_b2, out);
}